// round 3
// baseline (speedup 1.0000x reference)
#include <cuda_runtime.h>
#include <cuda_fp16.h>

#define B_ROWS   16384
#define K_FEATS  32
#define H_DIM    256
#define FULLMASK 0xFFFFFFFFu

#define TILE     8          // rows per block
#define XS_STRIDE 516       // floats per staged row (512 + 4 pad for bank-conflict-free 4-row reads)

// fp16 copy of ft_w: 40960 x 256 halves = 20MB (128 half2 per row)
__device__ __half2 g_ftw_h[40960 * 128];
// fc1_w transposed: [iq][j] float4 (iq over 512/4 inputs, j = 0..31 outputs)
__device__ float4 g_fc1T[128 * 32];

// ---- prep: fp32 -> fp16 table; 8 floats per thread, streaming reads ----
__global__ __launch_bounds__(256) void prep_ftw(const float* __restrict__ ft_w) {
    int i = blockIdx.x * blockDim.x + threadIdx.x;   // over 1,310,720 8-float chunks
    const float4 v0 = __ldcs((const float4*)ft_w + i * 2);
    const float4 v1 = __ldcs((const float4*)ft_w + i * 2 + 1);
    uint4 r;
    __half2 h0 = __floats2half2_rn(v0.x, v0.y);
    __half2 h1 = __floats2half2_rn(v0.z, v0.w);
    __half2 h2 = __floats2half2_rn(v1.x, v1.y);
    __half2 h3 = __floats2half2_rn(v1.z, v1.w);
    r.x = *(unsigned*)&h0; r.y = *(unsigned*)&h1;
    r.z = *(unsigned*)&h2; r.w = *(unsigned*)&h3;
    ((uint4*)g_ftw_h)[i] = r;
}

__global__ void prep_fc1(const float* __restrict__ fc1_w) {
    int t = blockIdx.x * blockDim.x + threadIdx.x;
    if (t < 128 * 32) {
        int iq = t >> 5;
        int j  = t & 31;
        const float* p = fc1_w + j * 512 + iq * 4;
        g_fc1T[t] = make_float4(p[0], p[1], p[2], p[3]);
    }
}

__device__ __forceinline__ float4 clip01(float4 v) {
    v.x = fminf(fmaxf(v.x, 0.0f), 1.0f);
    v.y = fminf(fmaxf(v.y, 0.0f), 1.0f);
    v.z = fminf(fmaxf(v.z, 0.0f), 1.0f);
    v.w = fminf(fmaxf(v.w, 0.0f), 1.0f);
    return v;
}

// accumulate 8 fp16 values (one uint4) scaled by m into two float4 accumulators
__device__ __forceinline__ void acc8(float4& a0, float4& a1, float m, uint4 r) {
    const __half2* h = (const __half2*)&r;
    float2 f0 = __half22float2(h[0]);
    float2 f1 = __half22float2(h[1]);
    float2 f2 = __half22float2(h[2]);
    float2 f3 = __half22float2(h[3]);
    a0.x = fmaf(m, f0.x, a0.x);  a0.y = fmaf(m, f0.y, a0.y);
    a0.z = fmaf(m, f1.x, a0.z);  a0.w = fmaf(m, f1.y, a0.w);
    a1.x = fmaf(m, f2.x, a1.x);  a1.y = fmaf(m, f2.y, a1.y);
    a1.z = fmaf(m, f3.x, a1.z);  a1.w = fmaf(m, f3.y, a1.w);
}

__global__ __launch_bounds__(128, 8)
void nnue_kernel(const int*   __restrict__ wft_ics,
                 const float* __restrict__ wft_vals,
                 const int*   __restrict__ bft_ics,
                 const float* __restrict__ bft_vals,
                 const int*   __restrict__ stm,
                 const float* __restrict__ ft_b,
                 const float* __restrict__ fc1_b,
                 const float* __restrict__ fc2_w,
                 const float* __restrict__ fc2_b,
                 const float* __restrict__ fco_w,
                 const float* __restrict__ fco_b,
                 float*       __restrict__ out)
{
    __shared__ int2  s_feat[2][TILE][K_FEATS];  // (.x = row offset in half2 units, .y = masked val bits)  4KB
    __shared__ float xs[TILE * XS_STRIDE];      // staged x[512] per row, fp32, padded stride   16.1KB
    __shared__ float fc2T[32 * 32];             // fc2T[i*32+j] = fc2_w[j][i]                    4KB
    __shared__ float h1s[TILE * 33];            // clipped FC1 activations                       ~1KB
    __shared__ int   s_stm[TILE];

    const int tid  = threadIdx.x;
    const int lane = tid & 31;
    const int warp = tid >> 5;
    const int row0 = blockIdx.x * TILE;

    // ---- staging: fc2 transpose, stm, and (offset, masked val) feature pairs ----
    for (int idx = tid; idx < 1024; idx += 128)
        fc2T[(idx & 31) * 32 + (idx >> 5)] = fc2_w[idx];
    if (tid < TILE)
        s_stm[tid] = stm[row0 + tid];

    #pragma unroll
    for (int idx = tid; idx < 2 * TILE * K_FEATS; idx += 128) {
        const int t   = idx >> 8;          // 0 = w, 1 = b
        const int rem = idx & 255;
        const int r   = rem >> 5;
        const int k   = rem & 31;
        const int gi  = (row0 + r) * K_FEATS + k;
        const int   i = t ? __ldg(bft_ics + gi)  : __ldg(wft_ics + gi);
        const float v = t ? __ldg(bft_vals + gi) : __ldg(wft_vals + gi);
        s_feat[t][r][k] = make_int2(i >= 0 ? i * 128 : 0,
                                    __float_as_int(i >= 0 ? v : 0.0f));
    }

    // per-lane ft bias (cols lane*8 .. lane*8+7)
    const float4 bias0 = *(const float4*)(ft_b + lane * 8);
    const float4 bias1 = *(const float4*)(ft_b + lane * 8 + 4);

    __syncthreads();

    // ---------------- Phase 1: gather (warp w -> rows 2w, 2w+1) ----------------
    #pragma unroll
    for (int rr = 0; rr < 2; rr++) {
        const int r = warp * 2 + rr;

        float4 aw0 = bias0, aw1 = bias1;
        float4 ab0 = bias0, ab1 = bias1;

        int2 pw = s_feat[0][r][0];
        int2 pb = s_feat[1][r][0];
        uint4 rw = __ldg((const uint4*)(g_ftw_h + pw.x) + lane);
        uint4 rb = __ldg((const uint4*)(g_ftw_h + pb.x) + lane);

        #pragma unroll 2
        for (int k = 0; k < K_FEATS; k++) {
            int2 pw1, pb1;
            uint4 rw1, rb1;
            if (k + 1 < K_FEATS) {
                pw1 = s_feat[0][r][k + 1];
                pb1 = s_feat[1][r][k + 1];
                rw1 = __ldg((const uint4*)(g_ftw_h + pw1.x) + lane);
                rb1 = __ldg((const uint4*)(g_ftw_h + pb1.x) + lane);
            }
            acc8(aw0, aw1, __int_as_float(pw.y), rw);
            acc8(ab0, ab1, __int_as_float(pb.y), rb);
            pw = pw1; pb = pb1; rw = rw1; rb = rb1;
        }

        // stm-conditional swap + clip, store fp32 x
        const int s = s_stm[r];
        float4 lo0, lo1, hi0, hi1;
        if (s) { lo0 = ab0; lo1 = ab1; hi0 = aw0; hi1 = aw1; }
        else   { lo0 = aw0; lo1 = aw1; hi0 = ab0; hi1 = ab1; }

        float4* xr = (float4*)(xs + r * XS_STRIDE);
        xr[lane * 2]          = clip01(lo0);
        xr[lane * 2 + 1]      = clip01(lo1);
        xr[64 + lane * 2]     = clip01(hi0);
        xr[64 + lane * 2 + 1] = clip01(hi1);
    }

    __syncthreads();

    // ---------------- Phase 2: FC1, mapping B ----------------
    // lane = rg*8 + jo ; output j = warp*8 + jo ; rows rg*2, rg*2+1
    const int jo = lane & 7;
    const int rg = lane >> 3;
    const int j  = warp * 8 + jo;
    const int r0 = rg * 2;

    float h1a = __ldg(fc1_b + j);
    float h1b = h1a;

    const float4* x0 = (const float4*)(xs + r0 * XS_STRIDE);
    const float4* x1 = (const float4*)(xs + (r0 + 1) * XS_STRIDE);

    #pragma unroll 4
    for (int iq = 0; iq < 128; iq++) {
        const float4 w  = g_fc1T[iq * 32 + j];  // 8 distinct float4 per warp = 128B, L1-hot
        const float4 xa = x0[iq];               // 4 distinct rows, conflict-free (padded stride)
        const float4 xb = x1[iq];
        h1a = fmaf(w.x, xa.x, fmaf(w.y, xa.y, fmaf(w.z, xa.z, fmaf(w.w, xa.w, h1a))));
        h1b = fmaf(w.x, xb.x, fmaf(w.y, xb.y, fmaf(w.z, xb.z, fmaf(w.w, xb.w, h1b))));
    }

    // clip and stage h1 for cross-warp FC2
    h1s[r0 * 33 + j]       = fminf(fmaxf(h1a, 0.0f), 1.0f);
    h1s[(r0 + 1) * 33 + j] = fminf(fmaxf(h1b, 0.0f), 1.0f);

    __syncthreads();

    // ---------------- FC2 + output head: warp handles rows 2*warp, 2*warp+1 ----------
    const float b2j = __ldg(fc2_b + lane);
    const float fcw = __ldg(fco_w + lane);
    const float fcb = __ldg(fco_b);

    #pragma unroll
    for (int rr = 0; rr < 2; rr++) {
        const int row = warp * 2 + rr;
        float h2 = b2j;
        #pragma unroll
        for (int i = 0; i < 32; i++)
            h2 = fmaf(fc2T[i * 32 + lane], h1s[row * 33 + i], h2);
        h2 = fminf(fmaxf(h2, 0.0f), 1.0f);

        float o = h2 * fcw;
        #pragma unroll
        for (int off = 16; off; off >>= 1)
            o += __shfl_xor_sync(FULLMASK, o, off);

        if (lane == 0)
            out[row0 + row] = o + fcb;
    }
}

extern "C" void kernel_launch(void* const* d_in, const int* in_sizes, int n_in,
                              void* d_out, int out_size)
{
    const int*   wft_ics  = (const int*)  d_in[0];
    const float* wft_vals = (const float*)d_in[1];
    const int*   bft_ics  = (const int*)  d_in[2];
    const float* bft_vals = (const float*)d_in[3];
    const int*   stm      = (const int*)  d_in[4];
    const float* ft_w     = (const float*)d_in[5];
    const float* ft_b     = (const float*)d_in[6];
    const float* fc1_w    = (const float*)d_in[7];
    const float* fc1_b    = (const float*)d_in[8];
    const float* fc2_w    = (const float*)d_in[9];
    const float* fc2_b    = (const float*)d_in[10];
    const float* fco_w    = (const float*)d_in[11];
    const float* fco_b    = (const float*)d_in[12];
    float* out = (float*)d_out;

    // 40960*256/8 = 1,310,720 chunks of 8 floats
    prep_ftw<<<5120, 256>>>(ft_w);
    prep_fc1<<<32, 128>>>(fc1_w);
    nnue_kernel<<<B_ROWS / TILE, 128>>>(wft_ics, wft_vals, bft_ics, bft_vals, stm,
                                        ft_b, fc1_b, fc2_w, fc2_b,
                                        fco_w, fco_b, out);
}

// round 4
// speedup vs baseline: 1.0326x; 1.0326x over previous
#include <cuda_runtime.h>
#include <cuda_fp16.h>

#define B_ROWS   16384
#define K_FEATS  32
#define H_DIM    256
#define FULLMASK 0xFFFFFFFFu

#define TILE      16        // rows per block
#define XS_STRIDE 516       // floats per staged row (512 + 4 pad, conflict-free)

// fp16 copy of ft_w: 40960 x 256 halves = 20MB (128 half2 per row)
__device__ __half2 g_ftw_h[40960 * 128];
// fc1_w transposed: [iq][j] float4 (iq over 512/4 inputs, j = 0..31 outputs)
__device__ float4 g_fc1T[128 * 32];

// ---- prep: fp32 -> fp16 table; 16 floats per thread, streaming reads ----
__global__ __launch_bounds__(256) void prep_ftw(const float* __restrict__ ft_w) {
    int i = blockIdx.x * blockDim.x + threadIdx.x;   // over 655,360 16-float chunks
    const float4* src = (const float4*)ft_w + i * 4;
    uint4* dst = (uint4*)g_ftw_h + i * 2;
    #pragma unroll
    for (int h = 0; h < 2; h++) {
        const float4 v0 = __ldcs(src + h * 2);
        const float4 v1 = __ldcs(src + h * 2 + 1);
        uint4 r;
        __half2 h0 = __floats2half2_rn(v0.x, v0.y);
        __half2 h1 = __floats2half2_rn(v0.z, v0.w);
        __half2 h2 = __floats2half2_rn(v1.x, v1.y);
        __half2 h3 = __floats2half2_rn(v1.z, v1.w);
        r.x = *(unsigned*)&h0; r.y = *(unsigned*)&h1;
        r.z = *(unsigned*)&h2; r.w = *(unsigned*)&h3;
        dst[h] = r;
    }
}

__global__ void prep_fc1(const float* __restrict__ fc1_w) {
    int t = blockIdx.x * blockDim.x + threadIdx.x;
    if (t < 128 * 32) {
        int iq = t >> 5;
        int j  = t & 31;
        const float* p = fc1_w + j * 512 + iq * 4;
        g_fc1T[t] = make_float4(p[0], p[1], p[2], p[3]);
    }
}

__device__ __forceinline__ float4 clip01(float4 v) {
    v.x = fminf(fmaxf(v.x, 0.0f), 1.0f);
    v.y = fminf(fmaxf(v.y, 0.0f), 1.0f);
    v.z = fminf(fmaxf(v.z, 0.0f), 1.0f);
    v.w = fminf(fmaxf(v.w, 0.0f), 1.0f);
    return v;
}

// accumulate 8 fp16 values (one uint4) scaled by m into two float4 accumulators
__device__ __forceinline__ void acc8(float4& a0, float4& a1, float m, uint4 r) {
    const __half2* h = (const __half2*)&r;
    float2 f0 = __half22float2(h[0]);
    float2 f1 = __half22float2(h[1]);
    float2 f2 = __half22float2(h[2]);
    float2 f3 = __half22float2(h[3]);
    a0.x = fmaf(m, f0.x, a0.x);  a0.y = fmaf(m, f0.y, a0.y);
    a0.z = fmaf(m, f1.x, a0.z);  a0.w = fmaf(m, f1.y, a0.w);
    a1.x = fmaf(m, f2.x, a1.x);  a1.y = fmaf(m, f2.y, a1.y);
    a1.z = fmaf(m, f3.x, a1.z);  a1.w = fmaf(m, f3.y, a1.w);
}

__global__ __launch_bounds__(256, 4)
void nnue_kernel(const int*   __restrict__ wft_ics,
                 const float* __restrict__ wft_vals,
                 const int*   __restrict__ bft_ics,
                 const float* __restrict__ bft_vals,
                 const int*   __restrict__ stm,
                 const float* __restrict__ ft_b,
                 const float* __restrict__ fc1_b,
                 const float* __restrict__ fc2_w,
                 const float* __restrict__ fc2_b,
                 const float* __restrict__ fco_w,
                 const float* __restrict__ fco_b,
                 float*       __restrict__ out)
{
    // s_feat[r][k] = (w_off_half2, w_val_bits, b_off_half2, b_val_bits)
    __shared__ int4  s_feat[TILE][K_FEATS];     // 8 KB
    __shared__ float xs[TILE * XS_STRIDE];      // staged x[512]/row fp32, padded  33 KB
    __shared__ float fc2T[32 * 32];             // fc2T[i*32+j] = fc2_w[j][i]      4 KB
    __shared__ float h1s[TILE * 33];            // clipped FC1 activations         2.1 KB
    __shared__ int   s_stm[TILE];

    const int tid  = threadIdx.x;
    const int lane = tid & 31;
    const int warp = tid >> 5;               // 0..7
    const int row0 = blockIdx.x * TILE;

    // ---- staging ----
    for (int idx = tid; idx < 1024; idx += 256)
        fc2T[(idx & 31) * 32 + (idx >> 5)] = fc2_w[idx];
    if (tid < TILE)
        s_stm[tid] = stm[row0 + tid];

    #pragma unroll
    for (int e = tid; e < TILE * K_FEATS; e += 256) {
        const int r  = e >> 5;
        const int k  = e & 31;
        const int gi = (row0 + r) * K_FEATS + k;
        const int   wi = __ldg(wft_ics + gi);
        const float wv = __ldg(wft_vals + gi);
        const int   bi = __ldg(bft_ics + gi);
        const float bv = __ldg(bft_vals + gi);
        s_feat[r][k] = make_int4(wi >= 0 ? wi * 128 : 0,
                                 __float_as_int(wi >= 0 ? wv : 0.0f),
                                 bi >= 0 ? bi * 128 : 0,
                                 __float_as_int(bi >= 0 ? bv : 0.0f));
    }

    // per-lane ft bias (cols lane*8 .. lane*8+7)
    const float4 bias0 = *(const float4*)(ft_b + lane * 8);
    const float4 bias1 = *(const float4*)(ft_b + lane * 8 + 4);

    __syncthreads();

    // ---------------- Phase 1: gather (warp w -> rows 2w, 2w+1) ----------------
    #pragma unroll
    for (int rr = 0; rr < 2; rr++) {
        const int r = warp * 2 + rr;

        float4 aw0 = bias0, aw1 = bias1;
        float4 ab0 = bias0, ab1 = bias1;

        #pragma unroll 2
        for (int k = 0; k < K_FEATS; k++) {
            const int4 f = s_feat[r][k];     // broadcast LDS.128
            const uint4 rw = __ldg((const uint4*)(g_ftw_h + f.x) + lane);
            const uint4 rb = __ldg((const uint4*)(g_ftw_h + f.z) + lane);
            acc8(aw0, aw1, __int_as_float(f.y), rw);
            acc8(ab0, ab1, __int_as_float(f.w), rb);
        }

        // stm-conditional swap + clip, store fp32 x
        const int s = s_stm[r];
        float4 lo0, lo1, hi0, hi1;
        if (s) { lo0 = ab0; lo1 = ab1; hi0 = aw0; hi1 = aw1; }
        else   { lo0 = aw0; lo1 = aw1; hi0 = ab0; hi1 = ab1; }

        float4* xr = (float4*)(xs + r * XS_STRIDE);
        xr[lane * 2]          = clip01(lo0);
        xr[lane * 2 + 1]      = clip01(lo1);
        xr[64 + lane * 2]     = clip01(hi0);
        xr[64 + lane * 2 + 1] = clip01(hi1);
    }

    __syncthreads();

    // ---------------- Phase 2: FC1 (lane j = output j; warp w -> rows 2w, 2w+1) ------
    const int j = lane;
    const float b1j = __ldg(fc1_b + j);
    float h1a = b1j, h1b = b1j;

    const int r0 = warp * 2;
    const float4* x0 = (const float4*)(xs + r0 * XS_STRIDE);
    const float4* x1 = (const float4*)(xs + (r0 + 1) * XS_STRIDE);

    #pragma unroll 4
    for (int iq = 0; iq < 128; iq++) {
        const float4 w  = g_fc1T[iq * 32 + j];  // coalesced 512B, L1-hot
        const float4 xa = x0[iq];               // broadcast LDS.128
        const float4 xb = x1[iq];
        h1a = fmaf(w.x, xa.x, fmaf(w.y, xa.y, fmaf(w.z, xa.z, fmaf(w.w, xa.w, h1a))));
        h1b = fmaf(w.x, xb.x, fmaf(w.y, xb.y, fmaf(w.z, xb.z, fmaf(w.w, xb.w, h1b))));
    }

    h1s[r0 * 33 + j]       = fminf(fmaxf(h1a, 0.0f), 1.0f);
    h1s[(r0 + 1) * 33 + j] = fminf(fmaxf(h1b, 0.0f), 1.0f);

    __syncthreads();

    // ---------------- FC2 + output head: warp w -> rows 2w, 2w+1 ----------------------
    const float b2j = __ldg(fc2_b + lane);
    const float fcw = __ldg(fco_w + lane);
    const float fcb = __ldg(fco_b);

    #pragma unroll
    for (int rr = 0; rr < 2; rr++) {
        const int row = warp * 2 + rr;
        float h2 = b2j;
        #pragma unroll
        for (int i = 0; i < 32; i++)
            h2 = fmaf(fc2T[i * 32 + lane], h1s[row * 33 + i], h2);
        h2 = fminf(fmaxf(h2, 0.0f), 1.0f);

        float o = h2 * fcw;
        #pragma unroll
        for (int off = 16; off; off >>= 1)
            o += __shfl_xor_sync(FULLMASK, o, off);

        if (lane == 0)
            out[row0 + row] = o + fcb;
    }
}

extern "C" void kernel_launch(void* const* d_in, const int* in_sizes, int n_in,
                              void* d_out, int out_size)
{
    const int*   wft_ics  = (const int*)  d_in[0];
    const float* wft_vals = (const float*)d_in[1];
    const int*   bft_ics  = (const int*)  d_in[2];
    const float* bft_vals = (const float*)d_in[3];
    const int*   stm      = (const int*)  d_in[4];
    const float* ft_w     = (const float*)d_in[5];
    const float* ft_b     = (const float*)d_in[6];
    const float* fc1_w    = (const float*)d_in[7];
    const float* fc1_b    = (const float*)d_in[8];
    const float* fc2_w    = (const float*)d_in[9];
    const float* fc2_b    = (const float*)d_in[10];
    const float* fco_w    = (const float*)d_in[11];
    const float* fco_b    = (const float*)d_in[12];
    float* out = (float*)d_out;

    // 40960*256/16 = 655,360 chunks of 16 floats
    prep_ftw<<<2560, 256>>>(ft_w);
    prep_fc1<<<32, 128>>>(fc1_w);
    nnue_kernel<<<B_ROWS / TILE, 256>>>(wft_ics, wft_vals, bft_ics, bft_vals, stm,
                                        ft_b, fc1_b, fc2_w, fc2_b,
                                        fco_w, fco_b, out);
}

// round 5
// speedup vs baseline: 1.0892x; 1.0548x over previous
#include <cuda_runtime.h>
#include <cuda_fp16.h>

#define B_ROWS   16384
#define K_FEATS  32
#define H_DIM    256
#define FULLMASK 0xFFFFFFFFu

#define TILE      16        // rows per block
#define XS_STRIDE 516       // floats per staged row (512 + 4 pad, conflict-free)

// fp16 copy of ft_w: 40960 x 256 halves = 20MB (128 half2 per row)
__device__ __half2 g_ftw_h[40960 * 128];
// fc1_w transposed: [iq][j] float4 (iq over 512/4 inputs, j = 0..31 outputs)
__device__ float4 g_fc1T[128 * 32];

// ---- prep: fp32 -> fp16 table; 8 floats per thread (measured-best shape, R3) ----
__global__ __launch_bounds__(256) void prep_ftw(const float* __restrict__ ft_w) {
    int i = blockIdx.x * blockDim.x + threadIdx.x;   // over 1,310,720 8-float chunks
    const float4 v0 = __ldcs((const float4*)ft_w + i * 2);
    const float4 v1 = __ldcs((const float4*)ft_w + i * 2 + 1);
    uint4 r;
    __half2 h0 = __floats2half2_rn(v0.x, v0.y);
    __half2 h1 = __floats2half2_rn(v0.z, v0.w);
    __half2 h2 = __floats2half2_rn(v1.x, v1.y);
    __half2 h3 = __floats2half2_rn(v1.z, v1.w);
    r.x = *(unsigned*)&h0; r.y = *(unsigned*)&h1;
    r.z = *(unsigned*)&h2; r.w = *(unsigned*)&h3;
    ((uint4*)g_ftw_h)[i] = r;
}

__global__ void prep_fc1(const float* __restrict__ fc1_w) {
    int t = blockIdx.x * blockDim.x + threadIdx.x;
    if (t < 128 * 32) {
        int iq = t >> 5;
        int j  = t & 31;
        const float* p = fc1_w + j * 512 + iq * 4;
        g_fc1T[t] = make_float4(p[0], p[1], p[2], p[3]);
    }
}

__device__ __forceinline__ float4 clip01(float4 v) {
    v.x = fminf(fmaxf(v.x, 0.0f), 1.0f);
    v.y = fminf(fmaxf(v.y, 0.0f), 1.0f);
    v.z = fminf(fmaxf(v.z, 0.0f), 1.0f);
    v.w = fminf(fmaxf(v.w, 0.0f), 1.0f);
    return v;
}

// accumulate 8 fp16 values (one uint4) scaled by m into two float4 accumulators
__device__ __forceinline__ void acc8(float4& a0, float4& a1, float m, uint4 r) {
    const __half2* h = (const __half2*)&r;
    float2 f0 = __half22float2(h[0]);
    float2 f1 = __half22float2(h[1]);
    float2 f2 = __half22float2(h[2]);
    float2 f3 = __half22float2(h[3]);
    a0.x = fmaf(m, f0.x, a0.x);  a0.y = fmaf(m, f0.y, a0.y);
    a0.z = fmaf(m, f1.x, a0.z);  a0.w = fmaf(m, f1.y, a0.w);
    a1.x = fmaf(m, f2.x, a1.x);  a1.y = fmaf(m, f2.y, a1.y);
    a1.z = fmaf(m, f3.x, a1.z);  a1.w = fmaf(m, f3.y, a1.w);
}

__global__ __launch_bounds__(256, 4)
void nnue_kernel(const int*   __restrict__ wft_ics,
                 const float* __restrict__ wft_vals,
                 const int*   __restrict__ bft_ics,
                 const float* __restrict__ bft_vals,
                 const int*   __restrict__ stm,
                 const float* __restrict__ ft_b,
                 const float* __restrict__ fc1_b,
                 const float* __restrict__ fc2_w,
                 const float* __restrict__ fc2_b,
                 const float* __restrict__ fco_w,
                 const float* __restrict__ fco_b,
                 float*       __restrict__ out)
{
    // s_feat[r][k] = (w_off_half2, w_val_bits, b_off_half2, b_val_bits); padded -> val_bits=0
    __shared__ int4  s_feat[TILE][K_FEATS];     // 8 KB
    __shared__ float xs[TILE * XS_STRIDE];      // staged x[512]/row fp32, padded  33 KB
    __shared__ float fc2T[32 * 32];             // fc2T[i*32+j] = fc2_w[j][i]      4 KB
    __shared__ float h1s[TILE * 33];            // clipped FC1 activations         2.1 KB
    __shared__ int   s_stm[TILE];

    const int tid  = threadIdx.x;
    const int lane = tid & 31;
    const int warp = tid >> 5;               // 0..7
    const int row0 = blockIdx.x * TILE;

    // ---- staging ----
    for (int idx = tid; idx < 1024; idx += 256)
        fc2T[(idx & 31) * 32 + (idx >> 5)] = fc2_w[idx];
    if (tid < TILE)
        s_stm[tid] = stm[row0 + tid];

    #pragma unroll
    for (int e = tid; e < TILE * K_FEATS; e += 256) {
        const int r  = e >> 5;
        const int k  = e & 31;
        const int gi = (row0 + r) * K_FEATS + k;
        const int   wi = __ldg(wft_ics + gi);
        const float wv = __ldg(wft_vals + gi);
        const int   bi = __ldg(bft_ics + gi);
        const float bv = __ldg(bft_vals + gi);
        s_feat[r][k] = make_int4(wi >= 0 ? wi * 128 : 0,
                                 __float_as_int(wi >= 0 ? wv : 0.0f),
                                 bi >= 0 ? bi * 128 : 0,
                                 __float_as_int(bi >= 0 ? bv : 0.0f));
    }

    // per-lane ft bias (cols lane*8 .. lane*8+7)
    const float4 bias0 = *(const float4*)(ft_b + lane * 8);
    const float4 bias1 = *(const float4*)(ft_b + lane * 8 + 4);

    __syncthreads();

    // ---------------- Phase 1: gather (warp w -> rows 2w, 2w+1) ----------------
    #pragma unroll
    for (int rr = 0; rr < 2; rr++) {
        const int r = warp * 2 + rr;

        float4 aw0 = bias0, aw1 = bias1;
        float4 ab0 = bias0, ab1 = bias1;

        #pragma unroll 4
        for (int k = 0; k < K_FEATS; k++) {
            const int4 f = s_feat[r][k];     // broadcast LDS.128 (warp-uniform)
            // uniform skip of padded slots (val bits == 0): no divergence, saves
            // the L1 wavefronts + FMAs of the dummy row-0 load (~10% of slots)
            if (f.y != 0) {
                const uint4 rw = __ldcg((const uint4*)(g_ftw_h + f.x) + lane);
                acc8(aw0, aw1, __int_as_float(f.y), rw);
            }
            if (f.w != 0) {
                const uint4 rb = __ldcg((const uint4*)(g_ftw_h + f.z) + lane);
                acc8(ab0, ab1, __int_as_float(f.w), rb);
            }
        }

        // stm-conditional swap + clip, store fp32 x
        const int s = s_stm[r];
        float4 lo0, lo1, hi0, hi1;
        if (s) { lo0 = ab0; lo1 = ab1; hi0 = aw0; hi1 = aw1; }
        else   { lo0 = aw0; lo1 = aw1; hi0 = ab0; hi1 = ab1; }

        float4* xr = (float4*)(xs + r * XS_STRIDE);
        xr[lane * 2]          = clip01(lo0);
        xr[lane * 2 + 1]      = clip01(lo1);
        xr[64 + lane * 2]     = clip01(hi0);
        xr[64 + lane * 2 + 1] = clip01(hi1);
    }

    __syncthreads();

    // ---------------- Phase 2: FC1 (lane j = output j; warp w -> rows 2w, 2w+1) ------
    const int j = lane;
    const float b1j = __ldg(fc1_b + j);
    float h1a = b1j, h1b = b1j;

    const int r0 = warp * 2;
    const float4* x0 = (const float4*)(xs + r0 * XS_STRIDE);
    const float4* x1 = (const float4*)(xs + (r0 + 1) * XS_STRIDE);

    #pragma unroll 4
    for (int iq = 0; iq < 128; iq++) {
        const float4 w  = g_fc1T[iq * 32 + j];  // coalesced 512B, L1-hot
        const float4 xa = x0[iq];               // broadcast LDS.128
        const float4 xb = x1[iq];
        h1a = fmaf(w.x, xa.x, fmaf(w.y, xa.y, fmaf(w.z, xa.z, fmaf(w.w, xa.w, h1a))));
        h1b = fmaf(w.x, xb.x, fmaf(w.y, xb.y, fmaf(w.z, xb.z, fmaf(w.w, xb.w, h1b))));
    }

    h1s[r0 * 33 + j]       = fminf(fmaxf(h1a, 0.0f), 1.0f);
    h1s[(r0 + 1) * 33 + j] = fminf(fmaxf(h1b, 0.0f), 1.0f);

    __syncthreads();

    // ---------------- FC2 + output head: warp w -> rows 2w, 2w+1 ----------------------
    const float b2j = __ldg(fc2_b + lane);
    const float fcw = __ldg(fco_w + lane);
    const float fcb = __ldg(fco_b);

    #pragma unroll
    for (int rr = 0; rr < 2; rr++) {
        const int row = warp * 2 + rr;
        float h2 = b2j;
        #pragma unroll
        for (int i = 0; i < 32; i++)
            h2 = fmaf(fc2T[i * 32 + lane], h1s[row * 33 + i], h2);
        h2 = fminf(fmaxf(h2, 0.0f), 1.0f);

        float o = h2 * fcw;
        #pragma unroll
        for (int off = 16; off; off >>= 1)
            o += __shfl_xor_sync(FULLMASK, o, off);

        if (lane == 0)
            out[row0 + row] = o + fcb;
    }
}

extern "C" void kernel_launch(void* const* d_in, const int* in_sizes, int n_in,
                              void* d_out, int out_size)
{
    const int*   wft_ics  = (const int*)  d_in[0];
    const float* wft_vals = (const float*)d_in[1];
    const int*   bft_ics  = (const int*)  d_in[2];
    const float* bft_vals = (const float*)d_in[3];
    const int*   stm      = (const int*)  d_in[4];
    const float* ft_w     = (const float*)d_in[5];
    const float* ft_b     = (const float*)d_in[6];
    const float* fc1_w    = (const float*)d_in[7];
    const float* fc1_b    = (const float*)d_in[8];
    const float* fc2_w    = (const float*)d_in[9];
    const float* fc2_b    = (const float*)d_in[10];
    const float* fco_w    = (const float*)d_in[11];
    const float* fco_b    = (const float*)d_in[12];
    float* out = (float*)d_out;

    // 40960*256/8 = 1,310,720 chunks of 8 floats
    prep_ftw<<<5120, 256>>>(ft_w);
    prep_fc1<<<32, 128>>>(fc1_w);
    nnue_kernel<<<B_ROWS / TILE, 256>>>(wft_ics, wft_vals, bft_ics, bft_vals, stm,
                                        ft_b, fc1_b, fc2_w, fc2_b,
                                        fco_w, fco_b, out);
}